// round 1
// baseline (speedup 1.0000x reference)
#include <cuda_runtime.h>
#include <cstdint>
#include <cstddef>

#define NN 100000
#define EE 1600000
#define FF 128
#define HH 128
#define LL 4
#define SS 10000
#define GG 256
#define CC 10

// ---------------- scratch (device globals; no allocation allowed) ----------------
__device__ int   d_deg[NN];
__device__ int   d_off[NN + 1];
__device__ int   d_cursor[NN];
__device__ int   d_csr[EE];
__device__ float d_u[(size_t)NN * HH];
__device__ float d_t[(size_t)NN * HH];
__device__ float d_z[(size_t)NN * HH];
__device__ float d_feat[(size_t)NN * LL * HH];   // [N, 512], layer l at cols [l*128, (l+1)*128)
__device__ float d_stats[2 * HH];                // sums[0:128], sumsq[128:256]
__device__ float d_scale[HH];
__device__ float d_shift[HH];
__device__ int   d_suboff[SS + 1];
__device__ int   d_gphoff[GG + 1];
__device__ float d_sub[(size_t)SS * LL * HH];
__device__ float d_gph[(size_t)GG * LL * HH];

// ---------------- f32x2 packed math (sm_100+) ----------------
__device__ __forceinline__ unsigned long long pack2(float lo, float hi) {
    unsigned long long r;
    asm("mov.b64 %0, {%1,%2};" : "=l"(r) : "f"(lo), "f"(hi));
    return r;
}
__device__ __forceinline__ void fma2(unsigned long long& d, unsigned long long a, unsigned long long b) {
    asm("fma.rn.f32x2 %0, %1, %2, %0;" : "+l"(d) : "l"(a), "l"(b));
}
__device__ __forceinline__ float2 unpack2(unsigned long long v) {
    float2 r;
    asm("mov.b64 {%0,%1}, %2;" : "=f"(r.x), "=f"(r.y) : "l"(v));
    return r;
}

// ---------------- CSR build ----------------
__global__ void zero_deg_kernel() {
    int i = blockIdx.x * blockDim.x + threadIdx.x;
    if (i < NN) d_deg[i] = 0;
}

__global__ void count_kernel(const int* __restrict__ dst) {
    int i = blockIdx.x * blockDim.x + threadIdx.x;
    if (i < EE) atomicAdd(&d_deg[dst[i]], 1);
}

__global__ void scan_kernel() {
    __shared__ int wsum[32];
    __shared__ int carry_s;
    int t = threadIdx.x, lane = t & 31, w = t >> 5;
    if (t == 0) carry_s = 0;
    __syncthreads();
    for (int base = 0; base < NN; base += 1024) {
        int carry = carry_s;
        int idx = base + t;
        int v = (idx < NN) ? d_deg[idx] : 0;
        int x = v;
#pragma unroll
        for (int d = 1; d < 32; d <<= 1) {
            int y = __shfl_up_sync(0xffffffffu, x, d);
            if (lane >= d) x += y;
        }
        if (lane == 31) wsum[w] = x;
        __syncthreads();
        if (w == 0) {
            int s = wsum[lane];
#pragma unroll
            for (int d = 1; d < 32; d <<= 1) {
                int y = __shfl_up_sync(0xffffffffu, s, d);
                if (lane >= d) s += y;
            }
            wsum[lane] = s;
        }
        __syncthreads();
        int woff = (w > 0) ? wsum[w - 1] : 0;
        int excl = carry + woff + x - v;
        if (idx < NN) { d_off[idx] = excl; d_cursor[idx] = excl; }
        int tot = wsum[31];
        __syncthreads();
        if (t == 0) carry_s = carry + tot;
        __syncthreads();
    }
    if (threadIdx.x == 0) d_off[NN] = carry_s;
}

__global__ void fill_kernel(const int* __restrict__ src, const int* __restrict__ dst) {
    int i = blockIdx.x * blockDim.x + threadIdx.x;
    if (i < EE) {
        int p = atomicAdd(&d_cursor[dst[i]], 1);
        d_csr[p] = src[i];
    }
}

// ---------------- aggregation: u = (1+eps)*x + sum_{nbr} x ----------------
__global__ void agg_kernel(const float* __restrict__ xin, int ldx,
                           const float* __restrict__ eps_ptr, int layer,
                           float* __restrict__ u) {
    int node = blockIdx.x * 8 + (threadIdx.x >> 5);
    if (node >= NN) return;
    int lane = threadIdx.x & 31;
    float e = 1.0f + eps_ptr[layer];
    int s = d_off[node], epos = d_off[node + 1];
    float4 acc = make_float4(0.f, 0.f, 0.f, 0.f);
    int j = s;
    for (; j + 2 <= epos; j += 2) {
        int s0 = d_csr[j], s1 = d_csr[j + 1];
        float4 v0 = *(const float4*)&xin[(size_t)s0 * ldx + lane * 4];
        float4 v1 = *(const float4*)&xin[(size_t)s1 * ldx + lane * 4];
        acc.x += v0.x + v1.x; acc.y += v0.y + v1.y;
        acc.z += v0.z + v1.z; acc.w += v0.w + v1.w;
    }
    if (j < epos) {
        int s0 = d_csr[j];
        float4 v0 = *(const float4*)&xin[(size_t)s0 * ldx + lane * 4];
        acc.x += v0.x; acc.y += v0.y; acc.z += v0.z; acc.w += v0.w;
    }
    float4 xv = *(const float4*)&xin[(size_t)node * ldx + lane * 4];
    float4 o;
    o.x = fmaf(e, xv.x, acc.x); o.y = fmaf(e, xv.y, acc.y);
    o.z = fmaf(e, xv.z, acc.z); o.w = fmaf(e, xv.w, acc.w);
    *(float4*)&u[(size_t)node * HH + lane * 4] = o;
}

// ---------------- GEMM: Y[N,128] = act(A)[N,128] @ W[128,128]^T + b ----------------
#define TM 64
#define US_STRIDE 132
#define WT_STRIDE 130
#define MM_SMEM ((TM * US_STRIDE + 128 * WT_STRIDE) * 4)

__global__ void __launch_bounds__(256, 2)
mm_kernel(const float* __restrict__ A, int lda,
          const float* __restrict__ W, const float* __restrict__ bias,
          const float* __restrict__ scale, const float* __restrict__ shift,
          float* __restrict__ Y, int nrows) {
    extern __shared__ float sm[];
    float* Us = sm;                      // [64][132]
    float* Wt = sm + TM * US_STRIDE;     // [128][130]  (Wt[k][o] = W[o][k])
    int tid = threadIdx.x;
    int row0 = blockIdx.x * TM;

#pragma unroll
    for (int i = tid; i < 128 * 128; i += 256) {
        int o = i >> 7, k = i & 127;
        Wt[k * WT_STRIDE + o] = W[i];
    }
#pragma unroll
    for (int i = tid; i < TM * 128; i += 256) {
        int r = i >> 7, k = i & 127;
        int gr = row0 + r;
        float v = 0.f;
        if (gr < nrows) {
            v = A[(size_t)gr * lda + k];
            if (scale) v = fmaxf(fmaf(v, scale[k], shift[k]), 0.f);
        }
        Us[r * US_STRIDE + k] = v;
    }
    __syncthreads();

    int lane = tid & 31, warp = tid >> 5;
    int cbase = warp * 16;
    unsigned long long acc0[8], acc1[8];
#pragma unroll
    for (int p = 0; p < 8; p++) { acc0[p] = 0ull; acc1[p] = 0ull; }
    const float* u0p = Us + lane * US_STRIDE;
    const float* u1p = Us + (lane + 32) * US_STRIDE;
    const float* wp = Wt + cbase;

#pragma unroll 4
    for (int k = 0; k < 128; k++) {
        float a0 = u0p[k], a1 = u1p[k];
        unsigned long long dd0 = pack2(a0, a0);
        unsigned long long dd1 = pack2(a1, a1);
        const float* wr = wp + k * WT_STRIDE;
#pragma unroll
        for (int p = 0; p < 8; p++) {
            unsigned long long w2 = *(const unsigned long long*)(wr + 2 * p);
            fma2(acc0[p], dd0, w2);
            fma2(acc1[p], dd1, w2);
        }
    }
    __syncthreads();

    // stage (with bias) in smem, then coalesced global store
    float* Ys = sm;  // [64][130], reuses Us/Wt space
#pragma unroll
    for (int p = 0; p < 8; p++) {
        int c = cbase + 2 * p;
        float bx = bias[c], by = bias[c + 1];
        float2 v0 = unpack2(acc0[p]); v0.x += bx; v0.y += by;
        float2 v1 = unpack2(acc1[p]); v1.x += bx; v1.y += by;
        *(float2*)&Ys[lane * WT_STRIDE + c] = v0;
        *(float2*)&Ys[(lane + 32) * WT_STRIDE + c] = v1;
    }
    __syncthreads();
#pragma unroll
    for (int i = tid; i < TM * 128; i += 256) {
        int r = i >> 7, k = i & 127;
        int gr = row0 + r;
        if (gr < nrows) Y[(size_t)gr * HH + k] = Ys[r * WT_STRIDE + k];
    }
}

// ---------------- BN ----------------
__global__ void zero_stats_kernel() {
    d_stats[threadIdx.x] = 0.f;
}

__global__ void stats_kernel(const float* __restrict__ v) {
    int col = threadIdx.x;  // 128 threads
    int per = (NN + gridDim.x - 1) / gridDim.x;
    int r0 = blockIdx.x * per;
    int r1 = r0 + per; if (r1 > NN) r1 = NN;
    float s = 0.f, s2 = 0.f;
    for (int r = r0; r < r1; r++) {
        float x = v[(size_t)r * HH + col];
        s += x;
        s2 = fmaf(x, x, s2);
    }
    atomicAdd(&d_stats[col], s);
    atomicAdd(&d_stats[HH + col], s2);
}

__global__ void bn_final_kernel(const float* __restrict__ gamma, const float* __restrict__ beta) {
    int c = threadIdx.x;
    const float inv_n = 1.0f / (float)NN;
    float mu = d_stats[c] * inv_n;
    float var = fmaf(-mu, mu, d_stats[HH + c] * inv_n);
    float rinv = rsqrtf(var + 1e-5f);
    float sc = rinv * gamma[c];
    d_scale[c] = sc;
    d_shift[c] = fmaf(-mu, sc, beta[c]);
}

__global__ void bnrelu_kernel(const float* __restrict__ z, float* __restrict__ featdst) {
    int i = blockIdx.x * blockDim.x + threadIdx.x;  // over NN*32 float4 groups
    if (i >= NN * 32) return;
    int r = i >> 5, c4 = i & 31;
    float4 v = *(const float4*)&z[(size_t)r * HH + c4 * 4];
    float4 sc = *(const float4*)&d_scale[c4 * 4];
    float4 sh = *(const float4*)&d_shift[c4 * 4];
    float4 o;
    o.x = fmaxf(fmaf(v.x, sc.x, sh.x), 0.f);
    o.y = fmaxf(fmaf(v.y, sc.y, sh.y), 0.f);
    o.z = fmaxf(fmaf(v.z, sc.z, sh.z), 0.f);
    o.w = fmaxf(fmaf(v.w, sc.w, sh.w), 0.f);
    *(float4*)&featdst[(size_t)r * (LL * HH) + c4 * 4] = o;
}

// ---------------- pooling ----------------
__global__ void lower_bound_kernel(const int* __restrict__ seg, int n, int* __restrict__ out, int nseg) {
    int s = blockIdx.x * blockDim.x + threadIdx.x;
    if (s > nseg) return;
    int lo = 0, hi = n;
    while (lo < hi) {
        int mid = (lo + hi) >> 1;
        if (seg[mid] < s) lo = mid + 1; else hi = mid;
    }
    out[s] = lo;
}

__global__ void segmean_kernel(const float* __restrict__ in, const int* __restrict__ off,
                               float* __restrict__ out) {
    int s = blockIdx.x, t = threadIdx.x;  // 128 threads, 4 cols each (512 total)
    int r0 = off[s], r1 = off[s + 1];
    float4 acc = make_float4(0.f, 0.f, 0.f, 0.f);
    for (int r = r0; r < r1; r++) {
        float4 v = *(const float4*)&in[(size_t)r * (LL * HH) + t * 4];
        acc.x += v.x; acc.y += v.y; acc.z += v.z; acc.w += v.w;
    }
    float inv = 1.0f / fmaxf((float)(r1 - r0), 1.0f);
    float4 o = make_float4(acc.x * inv, acc.y * inv, acc.z * inv, acc.w * inv);
    *(float4*)&out[(size_t)s * (LL * HH) + t * 4] = o;
}

// ---------------- head: lin1 + relu + lin2 + log_softmax ----------------
__global__ void head_kernel(const float* __restrict__ gph,
                            const float* __restrict__ w1, const float* __restrict__ bb1,
                            const float* __restrict__ w2, const float* __restrict__ bb2,
                            float* __restrict__ out) {
    __shared__ float grow[LL * HH];
    __shared__ float hbuf[HH];
    __shared__ float obuf[CC];
    int g = blockIdx.x, t = threadIdx.x;  // 128 threads
    for (int i = t; i < LL * HH; i += 128) grow[i] = gph[(size_t)g * (LL * HH) + i];
    __syncthreads();
    float acc = bb1[t];
#pragma unroll 8
    for (int k = 0; k < LL * HH; k++) acc = fmaf(grow[k], w1[(size_t)t * (LL * HH) + k], acc);
    hbuf[t] = fmaxf(acc, 0.f);
    __syncthreads();
    if (t < CC) {
        float a = bb2[t];
#pragma unroll 8
        for (int k = 0; k < HH; k++) a = fmaf(hbuf[k], w2[t * HH + k], a);
        obuf[t] = a;
    }
    __syncthreads();
    if (t == 0) {
        float m = obuf[0];
#pragma unroll
        for (int j = 1; j < CC; j++) m = fmaxf(m, obuf[j]);
        float se = 0.f;
#pragma unroll
        for (int j = 0; j < CC; j++) se += expf(obuf[j] - m);
        float lse = m + logf(se);
#pragma unroll
        for (int j = 0; j < CC; j++) out[g * CC + j] = obuf[j] - lse;
    }
}

// ---------------- launcher ----------------
extern "C" void kernel_launch(void* const* d_in, const int* in_sizes, int n_in,
                              void* d_out, int out_size) {
    const float* x     = (const float*)d_in[0];
    const int*   ei    = (const int*)d_in[1];
    const int*   n2s   = (const int*)d_in[2];
    const int*   s2g   = (const int*)d_in[3];
    const float* W1    = (const float*)d_in[4];
    const float* b1    = (const float*)d_in[5];
    const float* g1    = (const float*)d_in[6];
    const float* be1   = (const float*)d_in[7];
    const float* W2    = (const float*)d_in[8];
    const float* b2    = (const float*)d_in[9];
    const float* g2    = (const float*)d_in[10];
    const float* be2   = (const float*)d_in[11];
    const float* eps   = (const float*)d_in[12];
    const float* lin1W = (const float*)d_in[13];
    const float* lin1b = (const float*)d_in[14];
    const float* lin2W = (const float*)d_in[15];
    const float* lin2b = (const float*)d_in[16];
    float* out = (float*)d_out;

    void* p;
    cudaGetSymbolAddress(&p, d_u);      float* up     = (float*)p;
    cudaGetSymbolAddress(&p, d_t);      float* tp     = (float*)p;
    cudaGetSymbolAddress(&p, d_z);      float* zp     = (float*)p;
    cudaGetSymbolAddress(&p, d_feat);   float* featp  = (float*)p;
    cudaGetSymbolAddress(&p, d_scale);  float* scalep = (float*)p;
    cudaGetSymbolAddress(&p, d_shift);  float* shiftp = (float*)p;
    cudaGetSymbolAddress(&p, d_sub);    float* subp   = (float*)p;
    cudaGetSymbolAddress(&p, d_gph);    float* gphp   = (float*)p;
    cudaGetSymbolAddress(&p, d_suboff); int* suboffp  = (int*)p;
    cudaGetSymbolAddress(&p, d_gphoff); int* gphoffp  = (int*)p;

    cudaFuncSetAttribute(mm_kernel, cudaFuncAttributeMaxDynamicSharedMemorySize, MM_SMEM);

    const int* src = ei;
    const int* dst = ei + EE;

    // CSR build (reused by all 4 layers)
    zero_deg_kernel<<<(NN + 255) / 256, 256>>>();
    count_kernel<<<(EE + 255) / 256, 256>>>(dst);
    scan_kernel<<<1, 1024>>>();
    fill_kernel<<<(EE + 255) / 256, 256>>>(src, dst);

    const int mm_blocks = (NN + TM - 1) / TM;
    for (int l = 0; l < LL; l++) {
        const float* xin = (l == 0) ? x : (featp + (size_t)(l - 1) * HH);
        int ldx = (l == 0) ? FF : (LL * HH);
        agg_kernel<<<(NN + 7) / 8, 256>>>(xin, ldx, eps, l, up);

        // MLP linear 1
        mm_kernel<<<mm_blocks, 256, MM_SMEM>>>(up, HH, W1 + (size_t)l * HH * FF, b1 + l * HH,
                                               nullptr, nullptr, tp, NN);
        zero_stats_kernel<<<1, 2 * HH>>>();
        stats_kernel<<<1024, HH>>>(tp);
        bn_final_kernel<<<1, HH>>>(g1 + l * HH, be1 + l * HH);

        // MLP linear 2 with fused BN1+ReLU on input
        mm_kernel<<<mm_blocks, 256, MM_SMEM>>>(tp, HH, W2 + (size_t)l * HH * HH, b2 + l * HH,
                                               scalep, shiftp, zp, NN);
        zero_stats_kernel<<<1, 2 * HH>>>();
        stats_kernel<<<1024, HH>>>(zp);
        bn_final_kernel<<<1, HH>>>(g2 + l * HH, be2 + l * HH);

        // BN2 + ReLU -> feat slot l
        bnrelu_kernel<<<(NN * 32 + 255) / 256, 256>>>(zp, featp + (size_t)l * HH);
    }

    // pooling (segments are sorted -> binary-search offsets, deterministic means)
    lower_bound_kernel<<<(SS + 1 + 255) / 256, 256>>>(n2s, NN, suboffp, SS);
    lower_bound_kernel<<<(GG + 1 + 255) / 256, 256>>>(s2g, SS, gphoffp, GG);
    segmean_kernel<<<SS, 128>>>(featp, suboffp, subp);
    segmean_kernel<<<GG, 128>>>(subp, gphoffp, gphp);

    head_kernel<<<GG, 128>>>(gphp, lin1W, lin1b, lin2W, lin2b, out);
}